// round 1
// baseline (speedup 1.0000x reference)
#include <cuda_runtime.h>

#define B 8
#define QL 512
#define CL 2048
#define H 768
#define OUT 300
#define H4 3072

// Scratch (static device globals — allowed; no dynamic allocation anywhere)
__device__ float g_s[(size_t)B * CL * QL];      // S then softmax(a), 33.5 MB
__device__ float g_c2q[(size_t)B * CL * H];     // c2q, 50 MB
__device__ float g_m[B * CL];                   // row max of S
__device__ float g_sc[B * CL];
__device__ float g_sq[B * QL];
__device__ float g_batt[B * CL];
__device__ float g_q2cp[B * 8 * H];             // q2c partials (8 c-chunks)
__device__ float g_q2c[B * H];

// ---------------------------------------------------------------------------
// 1) sc = emb2 @ w_c + b_c   (B*CL rows),  sq = emb1 @ w_q + b_q (B*QL rows)
//    one warp per row
// ---------------------------------------------------------------------------
__global__ void k_dots(const float* __restrict__ emb1, const float* __restrict__ emb2,
                       const float* __restrict__ w_c, const float* __restrict__ b_c,
                       const float* __restrict__ w_q, const float* __restrict__ b_q) {
    int warp = (blockIdx.x * blockDim.x + threadIdx.x) >> 5;
    int lane = threadIdx.x & 31;
    const int n_sc = B * CL;
    const int total = n_sc + B * QL;
    if (warp >= total) return;
    const float* row; const float* w; float bias; float* out; int oi;
    if (warp < n_sc) { row = emb2 + (size_t)warp * H; w = w_c; bias = *b_c; out = g_sc; oi = warp; }
    else { int r = warp - n_sc; row = emb1 + (size_t)r * H; w = w_q; bias = *b_q; out = g_sq; oi = r; }
    float acc = 0.f;
    for (int i = lane * 4; i < H; i += 128) {
        float4 a = *(const float4*)(row + i);
        float4 ww = *(const float4*)(w + i);
        acc += a.x * ww.x + a.y * ww.y + a.z * ww.z + a.w * ww.w;
    }
    #pragma unroll
    for (int o = 16; o > 0; o >>= 1) acc += __shfl_xor_sync(0xffffffffu, acc, o);
    if (lane == 0) out[oi] = acc + bias;
}

// ---------------------------------------------------------------------------
// 2) S[b,c,q] = sum_h emb2[b,c,h]*w_cq[h]*emb1[b,q,h] + sc + sq + b_cq
//    NT SGEMM 128x128x8, 256 threads, 8x8 microtile
// ---------------------------------------------------------------------------
__global__ __launch_bounds__(256) void k_gemm_s(const float* __restrict__ emb1,
                                                const float* __restrict__ emb2,
                                                const float* __restrict__ w_cq,
                                                const float* __restrict__ b_cq) {
    __shared__ float As[8][128];
    __shared__ float Bs[8][128];
    int b = blockIdx.z;
    int m0 = blockIdx.y * 128;
    int n0 = blockIdx.x * 128;
    const float* Abase = emb2 + ((size_t)b * CL + m0) * H;
    const float* Bbase = emb1 + ((size_t)b * QL + n0) * H;
    int tid = threadIdx.x;
    int lrow = tid >> 1;
    int lk = (tid & 1) * 4;
    int tx = tid & 15, ty = tid >> 4;
    float acc[8][8];
    #pragma unroll
    for (int i = 0; i < 8; i++)
        #pragma unroll
        for (int j = 0; j < 8; j++) acc[i][j] = 0.f;

    for (int k0 = 0; k0 < H; k0 += 8) {
        float4 a4 = *(const float4*)(Abase + (size_t)lrow * H + k0 + lk);
        float4 w4 = *(const float4*)(w_cq + k0 + lk);
        a4.x *= w4.x; a4.y *= w4.y; a4.z *= w4.z; a4.w *= w4.w;
        float4 b4 = *(const float4*)(Bbase + (size_t)lrow * H + k0 + lk);
        As[lk + 0][lrow] = a4.x; As[lk + 1][lrow] = a4.y;
        As[lk + 2][lrow] = a4.z; As[lk + 3][lrow] = a4.w;
        Bs[lk + 0][lrow] = b4.x; Bs[lk + 1][lrow] = b4.y;
        Bs[lk + 2][lrow] = b4.z; Bs[lk + 3][lrow] = b4.w;
        __syncthreads();
        #pragma unroll
        for (int k = 0; k < 8; k++) {
            float ar[8], br[8];
            #pragma unroll
            for (int i = 0; i < 8; i++) ar[i] = As[k][ty * 8 + i];
            #pragma unroll
            for (int j = 0; j < 8; j++) br[j] = Bs[k][tx * 8 + j];
            #pragma unroll
            for (int i = 0; i < 8; i++)
                #pragma unroll
                for (int j = 0; j < 8; j++) acc[i][j] += ar[i] * br[j];
        }
        __syncthreads();
    }
    float bcq = *b_cq;
    #pragma unroll
    for (int i = 0; i < 8; i++) {
        int m = m0 + ty * 8 + i;
        float scv = g_sc[b * CL + m] + bcq;
        #pragma unroll
        for (int j = 0; j < 8; j++) {
            int n = n0 + tx * 8 + j;
            g_s[((size_t)b * CL + m) * QL + n] = acc[i][j] + scv + g_sq[b * QL + n];
        }
    }
}

// ---------------------------------------------------------------------------
// 3) row softmax over Q (512), in place; store row max into g_m
// ---------------------------------------------------------------------------
__global__ void k_softmax() {
    int row = blockIdx.x;  // 0 .. B*CL-1
    float* p = g_s + (size_t)row * QL;
    int tid = threadIdx.x; // 128
    float v[4];
    #pragma unroll
    for (int i = 0; i < 4; i++) v[i] = p[tid + i * 128];
    float mx = fmaxf(fmaxf(v[0], v[1]), fmaxf(v[2], v[3]));
    __shared__ float red[4];
    #pragma unroll
    for (int o = 16; o > 0; o >>= 1) mx = fmaxf(mx, __shfl_xor_sync(0xffffffffu, mx, o));
    if ((tid & 31) == 0) red[tid >> 5] = mx;
    __syncthreads();
    mx = fmaxf(fmaxf(red[0], red[1]), fmaxf(red[2], red[3]));
    float sum = 0.f;
    #pragma unroll
    for (int i = 0; i < 4; i++) { v[i] = __expf(v[i] - mx); sum += v[i]; }
    #pragma unroll
    for (int o = 16; o > 0; o >>= 1) sum += __shfl_xor_sync(0xffffffffu, sum, o);
    __shared__ float red2[4];
    if ((tid & 31) == 0) red2[tid >> 5] = sum;
    __syncthreads();
    sum = red2[0] + red2[1] + red2[2] + red2[3];
    float inv = 1.f / sum;
    #pragma unroll
    for (int i = 0; i < 4; i++) p[tid + i * 128] = v[i] * inv;
    if (tid == 0) g_m[row] = mx;
}

// ---------------------------------------------------------------------------
// 4) b_att[b,:] = softmax over C of g_m[b,:]
// ---------------------------------------------------------------------------
__global__ void k_batt() {
    int b = blockIdx.x;
    int tid = threadIdx.x; // 256
    const float* m = g_m + b * CL;
    float mx = -1e30f;
    for (int i = tid; i < CL; i += 256) mx = fmaxf(mx, m[i]);
    __shared__ float sm[8];
    #pragma unroll
    for (int o = 16; o > 0; o >>= 1) mx = fmaxf(mx, __shfl_xor_sync(0xffffffffu, mx, o));
    if ((tid & 31) == 0) sm[tid >> 5] = mx;
    __syncthreads();
    float bm = sm[0];
    #pragma unroll
    for (int i = 1; i < 8; i++) bm = fmaxf(bm, sm[i]);
    float sum = 0.f;
    for (int i = tid; i < CL; i += 256) sum += __expf(m[i] - bm);
    #pragma unroll
    for (int o = 16; o > 0; o >>= 1) sum += __shfl_xor_sync(0xffffffffu, sum, o);
    __shared__ float sm2[8];
    if ((tid & 31) == 0) sm2[tid >> 5] = sum;
    __syncthreads();
    float tot = 0.f;
    #pragma unroll
    for (int i = 0; i < 8; i++) tot += sm2[i];
    float inv = 1.f / tot;
    for (int i = tid; i < CL; i += 256) g_batt[b * CL + i] = __expf(m[i] - bm) * inv;
}

// ---------------------------------------------------------------------------
// 5a) q2c partials: each block reduces 256 c-rows for 128 h-columns
// ---------------------------------------------------------------------------
__global__ void k_q2c_part(const float* __restrict__ emb2) {
    int b = blockIdx.z;
    int cch = blockIdx.y;           // 0..7 (chunks of 256)
    int h = blockIdx.x * 128 + threadIdx.x;
    int c0 = cch * 256;
    float acc = 0.f;
    const float* base = emb2 + ((size_t)b * CL + c0) * H + h;
    const float* wb = g_batt + b * CL + c0;
    for (int c = 0; c < 256; c++) acc += wb[c] * base[(size_t)c * H];
    g_q2cp[((size_t)b * 8 + cch) * H + h] = acc;
}

// 5b) reduce partials
__global__ void k_q2c_reduce() {
    int b = blockIdx.x;
    for (int h = threadIdx.x; h < H; h += 256) {
        float s = 0.f;
        #pragma unroll
        for (int i = 0; i < 8; i++) s += g_q2cp[((size_t)b * 8 + i) * H + h];
        g_q2c[b * H + h] = s;
    }
}

// ---------------------------------------------------------------------------
// 6) c2q = a @ emb1 : NN SGEMM, M=CL, N=H, K=QL
// ---------------------------------------------------------------------------
__global__ __launch_bounds__(256) void k_gemm_c2q(const float* __restrict__ emb1) {
    __shared__ float As[8][128];
    __shared__ float Bs[8][128];
    int b = blockIdx.z;
    int m0 = blockIdx.y * 128;
    int n0 = blockIdx.x * 128;
    const float* Abase = g_s + ((size_t)b * CL + m0) * QL;
    const float* Bbase = emb1 + (size_t)b * QL * H + n0;
    int tid = threadIdx.x;
    int arow = tid >> 1, ak = (tid & 1) * 4;
    int brow = tid >> 5, bcol = (tid & 31) * 4;
    int tx = tid & 15, ty = tid >> 4;
    float acc[8][8];
    #pragma unroll
    for (int i = 0; i < 8; i++)
        #pragma unroll
        for (int j = 0; j < 8; j++) acc[i][j] = 0.f;

    for (int k0 = 0; k0 < QL; k0 += 8) {
        float4 a4 = *(const float4*)(Abase + (size_t)arow * QL + k0 + ak);
        float4 b4 = *(const float4*)(Bbase + (size_t)(k0 + brow) * H + bcol);
        As[ak + 0][arow] = a4.x; As[ak + 1][arow] = a4.y;
        As[ak + 2][arow] = a4.z; As[ak + 3][arow] = a4.w;
        *(float4*)&Bs[brow][bcol] = b4;
        __syncthreads();
        #pragma unroll
        for (int k = 0; k < 8; k++) {
            float ar[8], br[8];
            #pragma unroll
            for (int i = 0; i < 8; i++) ar[i] = As[k][ty * 8 + i];
            #pragma unroll
            for (int j = 0; j < 8; j++) br[j] = Bs[k][tx * 8 + j];
            #pragma unroll
            for (int i = 0; i < 8; i++)
                #pragma unroll
                for (int j = 0; j < 8; j++) acc[i][j] += ar[i] * br[j];
        }
        __syncthreads();
    }
    #pragma unroll
    for (int i = 0; i < 8; i++) {
        int m = m0 + ty * 8 + i;
        #pragma unroll
        for (int j = 0; j < 8; j++) {
            int n = n0 + tx * 8 + j;
            g_c2q[((size_t)b * CL + m) * H + n] = acc[i][j];
        }
    }
}

// ---------------------------------------------------------------------------
// 7) out[m,o] = sum_k e*W0' + cc*W1 + (e*cc)*W2 + b_red[o]
//    where W0'[o,k] = W0[o,k] + q2c[b,k]*W3[o,k] (folded at B-load)
//    BM=128, BN=64, BK=8, 256 threads, 8x4 microtile
// ---------------------------------------------------------------------------
__global__ __launch_bounds__(256) void k_red(const float* __restrict__ emb2,
                                             const float* __restrict__ w_red,
                                             const float* __restrict__ b_red,
                                             float* __restrict__ out) {
    __shared__ float Ae[8][128], Ac[8][128], Aec[8][128];
    __shared__ float Bs0[8][64], Bs1[8][64], Bs2[8][64];
    int m0 = blockIdx.y * 128;   // global row over B*CL
    int n0 = blockIdx.x * 64;
    int b = m0 / CL;
    int tid = threadIdx.x;
    int arow = tid >> 1, ak = (tid & 1) * 4;
    int tx = tid & 15, ty = tid >> 4;  // cols tx*4, rows ty*8
    float acc[8][4];
    #pragma unroll
    for (int i = 0; i < 8; i++)
        #pragma unroll
        for (int j = 0; j < 4; j++) acc[i][j] = 0.f;

    const float* Ebase = emb2 + (size_t)m0 * H;
    const float* Cbase = g_c2q + (size_t)m0 * H;
    const float* qq = g_q2c + b * H;

    for (int k0 = 0; k0 < H; k0 += 8) {
        float4 e4 = *(const float4*)(Ebase + (size_t)arow * H + k0 + ak);
        float4 c4 = *(const float4*)(Cbase + (size_t)arow * H + k0 + ak);
        Ae[ak + 0][arow] = e4.x; Ae[ak + 1][arow] = e4.y;
        Ae[ak + 2][arow] = e4.z; Ae[ak + 3][arow] = e4.w;
        Ac[ak + 0][arow] = c4.x; Ac[ak + 1][arow] = c4.y;
        Ac[ak + 2][arow] = c4.z; Ac[ak + 3][arow] = c4.w;
        Aec[ak + 0][arow] = e4.x * c4.x; Aec[ak + 1][arow] = e4.y * c4.y;
        Aec[ak + 2][arow] = e4.z * c4.z; Aec[ak + 3][arow] = e4.w * c4.w;
        if (tid < 128) {
            int n = tid >> 1;
            int o = n0 + n;
            int krel = (tid & 1) * 4;
            int kk = k0 + krel;
            float4 w0, w1, w2, w3;
            if (o < OUT) {
                const float* wr = w_red + (size_t)o * H4;
                w0 = *(const float4*)(wr + kk);
                w1 = *(const float4*)(wr + 768 + kk);
                w2 = *(const float4*)(wr + 1536 + kk);
                w3 = *(const float4*)(wr + 2304 + kk);
            } else {
                w0 = make_float4(0, 0, 0, 0); w1 = w0; w2 = w0; w3 = w0;
            }
            float4 q4 = *(const float4*)(qq + kk);
            Bs0[krel + 0][n] = w0.x + q4.x * w3.x;
            Bs0[krel + 1][n] = w0.y + q4.y * w3.y;
            Bs0[krel + 2][n] = w0.z + q4.z * w3.z;
            Bs0[krel + 3][n] = w0.w + q4.w * w3.w;
            Bs1[krel + 0][n] = w1.x; Bs1[krel + 1][n] = w1.y;
            Bs1[krel + 2][n] = w1.z; Bs1[krel + 3][n] = w1.w;
            Bs2[krel + 0][n] = w2.x; Bs2[krel + 1][n] = w2.y;
            Bs2[krel + 2][n] = w2.z; Bs2[krel + 3][n] = w2.w;
        }
        __syncthreads();
        #pragma unroll
        for (int k = 0; k < 8; k++) {
            float re[8], rc[8], rec[8];
            #pragma unroll
            for (int i = 0; i < 8; i++) {
                re[i] = Ae[k][ty * 8 + i];
                rc[i] = Ac[k][ty * 8 + i];
                rec[i] = Aec[k][ty * 8 + i];
            }
            float b0[4], b1[4], b2[4];
            #pragma unroll
            for (int j = 0; j < 4; j++) {
                b0[j] = Bs0[k][tx * 4 + j];
                b1[j] = Bs1[k][tx * 4 + j];
                b2[j] = Bs2[k][tx * 4 + j];
            }
            #pragma unroll
            for (int i = 0; i < 8; i++)
                #pragma unroll
                for (int j = 0; j < 4; j++)
                    acc[i][j] += re[i] * b0[j] + rc[i] * b1[j] + rec[i] * b2[j];
        }
        __syncthreads();
    }
    #pragma unroll
    for (int i = 0; i < 8; i++) {
        int m = m0 + ty * 8 + i;
        #pragma unroll
        for (int j = 0; j < 4; j++) {
            int o = n0 + tx * 4 + j;
            if (o < OUT) out[(size_t)m * OUT + o] = acc[i][j] + b_red[o];
        }
    }
}

// ---------------------------------------------------------------------------
extern "C" void kernel_launch(void* const* d_in, const int* in_sizes, int n_in,
                              void* d_out, int out_size) {
    (void)in_sizes; (void)n_in; (void)out_size;
    const float* emb1  = (const float*)d_in[0];
    const float* emb2  = (const float*)d_in[1];
    const float* w_c   = (const float*)d_in[2];
    const float* b_c   = (const float*)d_in[3];
    const float* w_q   = (const float*)d_in[4];
    const float* b_q   = (const float*)d_in[5];
    const float* w_cq  = (const float*)d_in[6];
    const float* b_cq  = (const float*)d_in[7];
    const float* w_red = (const float*)d_in[8];
    const float* b_red = (const float*)d_in[9];
    float* out = (float*)d_out;

    k_dots<<<2560, 256>>>(emb1, emb2, w_c, b_c, w_q, b_q);
    k_gemm_s<<<dim3(QL / 128, CL / 128, B), 256>>>(emb1, emb2, w_cq, b_cq);
    k_softmax<<<B * CL, 128>>>();
    k_batt<<<B, 256>>>();
    k_q2c_part<<<dim3(H / 128, 8, B), 128>>>(emb2);
    k_q2c_reduce<<<B, 256>>>();
    k_gemm_c2q<<<dim3(H / 128, CL / 128, B), 256>>>(emb1);
    k_red<<<dim3((OUT + 63) / 64, (B * CL) / 128), 256>>>(emb2, w_red, b_red, out);
}

// round 3
// speedup vs baseline: 2.1000x; 2.1000x over previous
#include <cuda_runtime.h>
#include <cuda_bf16.h>

#define B 8
#define QL 512
#define CL 2048
#define H 768
#define OUT 300
#define H4 3072

// ---------------- scratch (__device__ globals; no dynamic allocation) -------
__device__ float g_s[(size_t)B * CL * QL];          // raw logits S, 33.5 MB
__device__ float g_c2q[(size_t)B * CL * H];         // c2q fp32, 50 MB
__device__ float g_m[B * CL];
__device__ float g_sc[B * CL];
__device__ float g_sq[B * QL];
__device__ float g_batt[B * CL];
__device__ float g_q2cp[B * 8 * H];
__device__ float g_q2c[B * H];

__device__ __nv_bfloat16 g_e2wh[(size_t)B * CL * H];  // (emb2*w_cq) hi
__device__ __nv_bfloat16 g_e2wl[(size_t)B * CL * H];  // lo
__device__ __nv_bfloat16 g_e1h[(size_t)B * QL * H];   // emb1 hi  [q][h]
__device__ __nv_bfloat16 g_e1l[(size_t)B * QL * H];
__device__ __nv_bfloat16 g_e1th[(size_t)B * H * QL];  // emb1^T hi [h][q]
__device__ __nv_bfloat16 g_e1tl[(size_t)B * H * QL];
__device__ __nv_bfloat16 g_ah[(size_t)B * CL * QL];   // softmax probs hi
__device__ __nv_bfloat16 g_al[(size_t)B * CL * QL];

// ---------------- helpers ---------------------------------------------------
__device__ __forceinline__ float tf32r(float x) {
    unsigned r;
    asm("cvt.rna.tf32.f32 %0, %1;" : "=r"(r) : "f"(x));
    return __uint_as_float(r);
}

__device__ __forceinline__ void mma_bf16(float* c, const unsigned* a, unsigned b0, unsigned b1) {
    asm volatile(
        "mma.sync.aligned.m16n8k16.row.col.f32.bf16.bf16.f32 "
        "{%0,%1,%2,%3}, {%4,%5,%6,%7}, {%8,%9}, {%0,%1,%2,%3};\n"
        : "+f"(c[0]), "+f"(c[1]), "+f"(c[2]), "+f"(c[3])
        : "r"(a[0]), "r"(a[1]), "r"(a[2]), "r"(a[3]), "r"(b0), "r"(b1));
}

__device__ __forceinline__ void mma_tf32(float* c, const unsigned* a, unsigned b0, unsigned b1) {
    asm volatile(
        "mma.sync.aligned.m16n8k8.row.col.f32.tf32.tf32.f32 "
        "{%0,%1,%2,%3}, {%4,%5,%6,%7}, {%8,%9}, {%0,%1,%2,%3};\n"
        : "+f"(c[0]), "+f"(c[1]), "+f"(c[2]), "+f"(c[3])
        : "r"(a[0]), "r"(a[1]), "r"(a[2]), "r"(a[3]), "r"(b0), "r"(b1));
}

__device__ __forceinline__ unsigned ldb2(const __nv_bfloat16* p) {
    return *(const unsigned*)p;
}

__device__ __forceinline__ void split4(float4 v, uint2& hi, uint2& lo) {
    __nv_bfloat16 h[4], l[4];
    float f[4] = {v.x, v.y, v.z, v.w};
    #pragma unroll
    for (int i = 0; i < 4; i++) {
        h[i] = __float2bfloat16(f[i]);
        l[i] = __float2bfloat16(f[i] - __bfloat162float(h[i]));
    }
    hi = *(uint2*)h; lo = *(uint2*)l;
}

// ---------------- prep 1: bf16 split of emb2*w_cq and emb1 ------------------
#define NA4 (B * CL * H / 4)   // 3,145,728 float4 slots for e2w
#define NB4 (B * QL * H / 4)   // 786,432 for e1
__global__ void k_prep1(const float* __restrict__ emb1, const float* __restrict__ emb2,
                        const float* __restrict__ w_cq) {
    int i = blockIdx.x * blockDim.x + threadIdx.x;
    if (i < NA4) {
        size_t i0 = (size_t)i * 4;
        int h0 = (int)(i0 % H);
        float4 e = *(const float4*)(emb2 + i0);
        float4 w = *(const float4*)(w_cq + h0);
        float4 x = make_float4(e.x * w.x, e.y * w.y, e.z * w.z, e.w * w.w);
        uint2 hi, lo; split4(x, hi, lo);
        *(uint2*)(g_e2wh + i0) = hi;
        *(uint2*)(g_e2wl + i0) = lo;
    } else if (i < NA4 + NB4) {
        size_t i0 = (size_t)(i - NA4) * 4;
        float4 x = *(const float4*)(emb1 + i0);
        uint2 hi, lo; split4(x, hi, lo);
        *(uint2*)(g_e1h + i0) = hi;
        *(uint2*)(g_e1l + i0) = lo;
    }
}

// ---------------- prep 2: transposed emb1^T (bf16 split) --------------------
__global__ void k_prep2(const float* __restrict__ emb1) {
    __shared__ float tile[32][33];
    int b = blockIdx.z;
    int h0 = blockIdx.x * 32, q0 = blockIdx.y * 32;
    int tx = threadIdx.x, ty = threadIdx.y;  // 32 x 8
    #pragma unroll
    for (int i = 0; i < 4; i++) {
        int q = q0 + ty + i * 8;
        tile[ty + i * 8][tx] = emb1[((size_t)b * QL + q) * H + h0 + tx];
    }
    __syncthreads();
    #pragma unroll
    for (int i = 0; i < 4; i++) {
        int h = h0 + ty + i * 8;
        float v = tile[tx][ty + i * 8];
        __nv_bfloat16 hi = __float2bfloat16(v);
        __nv_bfloat16 lo = __float2bfloat16(v - __bfloat162float(hi));
        size_t o = ((size_t)b * H + h) * QL + q0 + tx;
        g_e1th[o] = hi;
        g_e1tl[o] = lo;
    }
}

// ---------------- sc / sq ---------------------------------------------------
__global__ void k_dots(const float* __restrict__ emb1, const float* __restrict__ emb2,
                       const float* __restrict__ w_c, const float* __restrict__ b_c,
                       const float* __restrict__ w_q, const float* __restrict__ b_q) {
    int warp = (blockIdx.x * blockDim.x + threadIdx.x) >> 5;
    int lane = threadIdx.x & 31;
    const int n_sc = B * CL;
    const int total = n_sc + B * QL;
    if (warp >= total) return;
    const float* row; const float* w; float bias; float* out; int oi;
    if (warp < n_sc) { row = emb2 + (size_t)warp * H; w = w_c; bias = *b_c; out = g_sc; oi = warp; }
    else { int r = warp - n_sc; row = emb1 + (size_t)r * H; w = w_q; bias = *b_q; out = g_sq; oi = r; }
    float acc = 0.f;
    for (int i = lane * 4; i < H; i += 128) {
        float4 a = *(const float4*)(row + i);
        float4 ww = *(const float4*)(w + i);
        acc += a.x * ww.x + a.y * ww.y + a.z * ww.z + a.w * ww.w;
    }
    #pragma unroll
    for (int o = 16; o > 0; o >>= 1) acc += __shfl_xor_sync(0xffffffffu, acc, o);
    if (lane == 0) out[oi] = acc + bias;
}

// ---------------- S GEMM (NT, bf16 split mma) -------------------------------
// S[c,q] = sum_h (emb2*w_cq)[c,h] * emb1[q,h] + sc + sq + bcq
__global__ __launch_bounds__(256) void k_gemm_s_mma(const float* __restrict__ b_cq) {
    __shared__ __nv_bfloat16 Ash[128 * 40], Asl[128 * 40];
    __shared__ __nv_bfloat16 Bsh[128 * 40], Bsl[128 * 40];
    int b = blockIdx.z, m0 = blockIdx.y * 128, n0 = blockIdx.x * 128;
    int tid = threadIdx.x, lane = tid & 31, w = tid >> 5;
    int wm = w >> 1, wn = w & 1, g = lane >> 2, tg = lane & 3;
    const __nv_bfloat16* Ah = g_e2wh + (size_t)(b * CL + m0) * H;
    const __nv_bfloat16* Al = g_e2wl + (size_t)(b * CL + m0) * H;
    const __nv_bfloat16* Bh = g_e1h + (size_t)(b * QL + n0) * H;
    const __nv_bfloat16* Bl = g_e1l + (size_t)(b * QL + n0) * H;

    float acc[2][8][4];
    #pragma unroll
    for (int i = 0; i < 2; i++)
        #pragma unroll
        for (int j = 0; j < 8; j++)
            #pragma unroll
            for (int k = 0; k < 4; k++) acc[i][j][k] = 0.f;

    for (int k0 = 0; k0 < H; k0 += 32) {
        #pragma unroll
        for (int s = 0; s < 2; s++) {
            int id = tid + s * 256;
            int row = id >> 2, kc = (id & 3) * 8;
            *(uint4*)&Ash[row * 40 + kc] = *(const uint4*)&Ah[(size_t)row * H + k0 + kc];
            *(uint4*)&Asl[row * 40 + kc] = *(const uint4*)&Al[(size_t)row * H + k0 + kc];
            *(uint4*)&Bsh[row * 40 + kc] = *(const uint4*)&Bh[(size_t)row * H + k0 + kc];
            *(uint4*)&Bsl[row * 40 + kc] = *(const uint4*)&Bl[(size_t)row * H + k0 + kc];
        }
        __syncthreads();
        #pragma unroll
        for (int ks = 0; ks < 32; ks += 16) {
            unsigned bh0[8], bh1[8], bl0[8], bl1[8];
            #pragma unroll
            for (int ni = 0; ni < 8; ni++) {
                int off = (wn * 64 + ni * 8 + g) * 40 + ks + 2 * tg;
                bh0[ni] = ldb2(&Bsh[off]); bh1[ni] = ldb2(&Bsh[off + 8]);
                bl0[ni] = ldb2(&Bsl[off]); bl1[ni] = ldb2(&Bsl[off + 8]);
            }
            #pragma unroll
            for (int mi = 0; mi < 2; mi++) {
                int ra = (wm * 32 + mi * 16 + g) * 40 + ks + 2 * tg;
                unsigned ah[4] = { ldb2(&Ash[ra]), ldb2(&Ash[ra + 8 * 40]),
                                   ldb2(&Ash[ra + 8]), ldb2(&Ash[ra + 8 * 40 + 8]) };
                unsigned al[4] = { ldb2(&Asl[ra]), ldb2(&Asl[ra + 8 * 40]),
                                   ldb2(&Asl[ra + 8]), ldb2(&Asl[ra + 8 * 40 + 8]) };
                #pragma unroll
                for (int ni = 0; ni < 8; ni++) {
                    mma_bf16(acc[mi][ni], ah, bh0[ni], bh1[ni]);
                    mma_bf16(acc[mi][ni], ah, bl0[ni], bl1[ni]);
                    mma_bf16(acc[mi][ni], al, bh0[ni], bh1[ni]);
                }
            }
        }
        __syncthreads();
    }

    float bcqv = *b_cq;
    #pragma unroll
    for (int mi = 0; mi < 2; mi++) {
        int r0 = m0 + wm * 32 + mi * 16 + g;
        int r1 = r0 + 8;
        float sc0 = g_sc[b * CL + r0] + bcqv;
        float sc1 = g_sc[b * CL + r1] + bcqv;
        #pragma unroll
        for (int ni = 0; ni < 8; ni++) {
            int cc = n0 + wn * 64 + ni * 8 + 2 * tg;
            float sq0 = g_sq[b * QL + cc], sq1 = g_sq[b * QL + cc + 1];
            float* a4 = acc[mi][ni];
            *(float2*)&g_s[((size_t)b * CL + r0) * QL + cc] =
                make_float2(a4[0] + sc0 + sq0, a4[1] + sc0 + sq1);
            *(float2*)&g_s[((size_t)b * CL + r1) * QL + cc] =
                make_float2(a4[2] + sc1 + sq0, a4[3] + sc1 + sq1);
        }
    }
}

// ---------------- softmax over Q, emit bf16 split probs + row max -----------
__global__ void k_softmax() {
    int row = blockIdx.x;
    const float* p = g_s + (size_t)row * QL;
    int tid = threadIdx.x;  // 128
    float v[4];
    #pragma unroll
    for (int i = 0; i < 4; i++) v[i] = p[tid + i * 128];
    float mx = fmaxf(fmaxf(v[0], v[1]), fmaxf(v[2], v[3]));
    __shared__ float red[4];
    #pragma unroll
    for (int o = 16; o > 0; o >>= 1) mx = fmaxf(mx, __shfl_xor_sync(0xffffffffu, mx, o));
    if ((tid & 31) == 0) red[tid >> 5] = mx;
    __syncthreads();
    mx = fmaxf(fmaxf(red[0], red[1]), fmaxf(red[2], red[3]));
    float sum = 0.f;
    #pragma unroll
    for (int i = 0; i < 4; i++) { v[i] = __expf(v[i] - mx); sum += v[i]; }
    #pragma unroll
    for (int o = 16; o > 0; o >>= 1) sum += __shfl_xor_sync(0xffffffffu, sum, o);
    __shared__ float red2[4];
    if ((tid & 31) == 0) red2[tid >> 5] = sum;
    __syncthreads();
    sum = red2[0] + red2[1] + red2[2] + red2[3];
    float inv = 1.f / sum;
    #pragma unroll
    for (int i = 0; i < 4; i++) {
        float pv = v[i] * inv;
        __nv_bfloat16 hi = __float2bfloat16(pv);
        size_t o = (size_t)row * QL + tid + i * 128;
        g_ah[o] = hi;
        g_al[o] = __float2bfloat16(pv - __bfloat162float(hi));
    }
    if (tid == 0) g_m[row] = mx;
}

// ---------------- b_att -----------------------------------------------------
__global__ void k_batt() {
    int b = blockIdx.x;
    int tid = threadIdx.x;  // 256
    const float* m = g_m + b * CL;
    float mx = -1e30f;
    for (int i = tid; i < CL; i += 256) mx = fmaxf(mx, m[i]);
    __shared__ float sm[8];
    #pragma unroll
    for (int o = 16; o > 0; o >>= 1) mx = fmaxf(mx, __shfl_xor_sync(0xffffffffu, mx, o));
    if ((tid & 31) == 0) sm[tid >> 5] = mx;
    __syncthreads();
    float bm = sm[0];
    #pragma unroll
    for (int i = 1; i < 8; i++) bm = fmaxf(bm, sm[i]);
    float sum = 0.f;
    for (int i = tid; i < CL; i += 256) sum += __expf(m[i] - bm);
    #pragma unroll
    for (int o = 16; o > 0; o >>= 1) sum += __shfl_xor_sync(0xffffffffu, sum, o);
    __shared__ float sm2[8];
    if ((tid & 31) == 0) sm2[tid >> 5] = sum;
    __syncthreads();
    float tot = 0.f;
    #pragma unroll
    for (int i = 0; i < 8; i++) tot += sm2[i];
    float inv = 1.f / tot;
    for (int i = tid; i < CL; i += 256) g_batt[b * CL + i] = __expf(m[i] - bm) * inv;
}

// ---------------- q2c -------------------------------------------------------
__global__ void k_q2c_part(const float* __restrict__ emb2) {
    int b = blockIdx.z;
    int cch = blockIdx.y;
    int h = blockIdx.x * 128 + threadIdx.x;
    int c0 = cch * 256;
    float acc = 0.f;
    const float* base = emb2 + ((size_t)b * CL + c0) * H + h;
    const float* wb = g_batt + b * CL + c0;
    for (int c = 0; c < 256; c++) acc += wb[c] * base[(size_t)c * H];
    g_q2cp[((size_t)b * 8 + cch) * H + h] = acc;
}

__global__ void k_q2c_reduce() {
    int b = blockIdx.x;
    for (int h = threadIdx.x; h < H; h += 256) {
        float s = 0.f;
        #pragma unroll
        for (int i = 0; i < 8; i++) s += g_q2cp[((size_t)b * 8 + i) * H + h];
        g_q2c[b * H + h] = s;
    }
}

// ---------------- c2q GEMM (NT on transposed emb1, bf16 split mma) ----------
// c2q[c,h] = sum_q a[c,q] * emb1T[h,q]
__global__ __launch_bounds__(256) void k_gemm_c2q_mma() {
    __shared__ __nv_bfloat16 Ash[128 * 40], Asl[128 * 40];
    __shared__ __nv_bfloat16 Bsh[128 * 40], Bsl[128 * 40];
    int b = blockIdx.z, m0 = blockIdx.y * 128, n0 = blockIdx.x * 128;
    int tid = threadIdx.x, lane = tid & 31, w = tid >> 5;
    int wm = w >> 1, wn = w & 1, g = lane >> 2, tg = lane & 3;
    const __nv_bfloat16* Ah = g_ah + (size_t)(b * CL + m0) * QL;
    const __nv_bfloat16* Al = g_al + (size_t)(b * CL + m0) * QL;
    const __nv_bfloat16* Bh = g_e1th + ((size_t)b * H + n0) * QL;
    const __nv_bfloat16* Bl = g_e1tl + ((size_t)b * H + n0) * QL;

    float acc[2][8][4];
    #pragma unroll
    for (int i = 0; i < 2; i++)
        #pragma unroll
        for (int j = 0; j < 8; j++)
            #pragma unroll
            for (int k = 0; k < 4; k++) acc[i][j][k] = 0.f;

    for (int k0 = 0; k0 < QL; k0 += 32) {
        #pragma unroll
        for (int s = 0; s < 2; s++) {
            int id = tid + s * 256;
            int row = id >> 2, kc = (id & 3) * 8;
            *(uint4*)&Ash[row * 40 + kc] = *(const uint4*)&Ah[(size_t)row * QL + k0 + kc];
            *(uint4*)&Asl[row * 40 + kc] = *(const uint4*)&Al[(size_t)row * QL + k0 + kc];
            *(uint4*)&Bsh[row * 40 + kc] = *(const uint4*)&Bh[(size_t)row * QL + k0 + kc];
            *(uint4*)&Bsl[row * 40 + kc] = *(const uint4*)&Bl[(size_t)row * QL + k0 + kc];
        }
        __syncthreads();
        #pragma unroll
        for (int ks = 0; ks < 32; ks += 16) {
            unsigned bh0[8], bh1[8], bl0[8], bl1[8];
            #pragma unroll
            for (int ni = 0; ni < 8; ni++) {
                int off = (wn * 64 + ni * 8 + g) * 40 + ks + 2 * tg;
                bh0[ni] = ldb2(&Bsh[off]); bh1[ni] = ldb2(&Bsh[off + 8]);
                bl0[ni] = ldb2(&Bsl[off]); bl1[ni] = ldb2(&Bsl[off + 8]);
            }
            #pragma unroll
            for (int mi = 0; mi < 2; mi++) {
                int ra = (wm * 32 + mi * 16 + g) * 40 + ks + 2 * tg;
                unsigned ah[4] = { ldb2(&Ash[ra]), ldb2(&Ash[ra + 8 * 40]),
                                   ldb2(&Ash[ra + 8]), ldb2(&Ash[ra + 8 * 40 + 8]) };
                unsigned al[4] = { ldb2(&Asl[ra]), ldb2(&Asl[ra + 8 * 40]),
                                   ldb2(&Asl[ra + 8]), ldb2(&Asl[ra + 8 * 40 + 8]) };
                #pragma unroll
                for (int ni = 0; ni < 8; ni++) {
                    mma_bf16(acc[mi][ni], ah, bh0[ni], bh1[ni]);
                    mma_bf16(acc[mi][ni], ah, bl0[ni], bl1[ni]);
                    mma_bf16(acc[mi][ni], al, bh0[ni], bh1[ni]);
                }
            }
        }
        __syncthreads();
    }

    #pragma unroll
    for (int mi = 0; mi < 2; mi++) {
        int r0 = m0 + wm * 32 + mi * 16 + g;
        int r1 = r0 + 8;
        #pragma unroll
        for (int ni = 0; ni < 8; ni++) {
            int cc = n0 + wn * 64 + ni * 8 + 2 * tg;
            float* a4 = acc[mi][ni];
            *(float2*)&g_c2q[((size_t)b * CL + r0) * H + cc] = make_float2(a4[0], a4[1]);
            *(float2*)&g_c2q[((size_t)b * CL + r1) * H + cc] = make_float2(a4[2], a4[3]);
        }
    }
}

// ---------------- reduction GEMM (tf32 mma, 3 streams, q2c folded) ----------
__global__ __launch_bounds__(256) void k_red_mma(const float* __restrict__ emb2,
                                                 const float* __restrict__ w_red,
                                                 const float* __restrict__ b_red,
                                                 float* __restrict__ out) {
    __shared__ float Ae[128 * 20], Ac[128 * 20], Aec[128 * 20];
    __shared__ float Bs0[64 * 20], Bs1[64 * 20], Bs2[64 * 20];
    int m0 = blockIdx.y * 128, n0 = blockIdx.x * 64;
    int b = m0 / CL;
    int tid = threadIdx.x, lane = tid & 31, w = tid >> 5;
    int wm = w >> 1, wn = w & 1, g = lane >> 2, tg = lane & 3;
    const float* Eb = emb2 + (size_t)m0 * H;
    const float* Cb = g_c2q + (size_t)m0 * H;
    const float* qq = g_q2c + b * H;

    float acc[2][4][4];
    #pragma unroll
    for (int i = 0; i < 2; i++)
        #pragma unroll
        for (int j = 0; j < 4; j++)
            #pragma unroll
            for (int k = 0; k < 4; k++) acc[i][j][k] = 0.f;

    for (int k0 = 0; k0 < H; k0 += 16) {
        // A tiles: emb2, c2q, product  (128 x 16)
        #pragma unroll
        for (int s = 0; s < 2; s++) {
            int id = tid + s * 256;
            int row = id >> 2, c4 = (id & 3) * 4;
            float4 e = *(const float4*)&Eb[(size_t)row * H + k0 + c4];
            float4 c = *(const float4*)&Cb[(size_t)row * H + k0 + c4];
            int o = row * 20 + c4;
            *(float4*)&Ae[o] = make_float4(tf32r(e.x), tf32r(e.y), tf32r(e.z), tf32r(e.w));
            *(float4*)&Ac[o] = make_float4(tf32r(c.x), tf32r(c.y), tf32r(c.z), tf32r(c.w));
            *(float4*)&Aec[o] = make_float4(tf32r(e.x * c.x), tf32r(e.y * c.y),
                                            tf32r(e.z * c.z), tf32r(e.w * c.w));
        }
        // B tiles: w0+q2c*w3, w1, w2  (64 x 16)
        {
            int row = tid >> 2, c4 = (tid & 3) * 4;
            int o = n0 + row;
            float4 w0, w1, w2, w3, q;
            if (o < OUT) {
                const float* wr = w_red + (size_t)o * H4 + k0 + c4;
                w0 = *(const float4*)(wr);
                w1 = *(const float4*)(wr + 768);
                w2 = *(const float4*)(wr + 1536);
                w3 = *(const float4*)(wr + 2304);
                q = *(const float4*)&qq[k0 + c4];
            } else {
                w0 = make_float4(0, 0, 0, 0); w1 = w0; w2 = w0; w3 = w0; q = w0;
            }
            int so = row * 20 + c4;
            *(float4*)&Bs0[so] = make_float4(tf32r(w0.x + q.x * w3.x), tf32r(w0.y + q.y * w3.y),
                                             tf32r(w0.z + q.z * w3.z), tf32r(w0.w + q.w * w3.w));
            *(float4*)&Bs1[so] = make_float4(tf32r(w1.x), tf32r(w1.y), tf32r(w1.z), tf32r(w1.w));
            *(float4*)&Bs2[so] = make_float4(tf32r(w2.x), tf32r(w2.y), tf32r(w2.z), tf32r(w2.w));
        }
        __syncthreads();
        #pragma unroll
        for (int ks = 0; ks < 16; ks += 8) {
            unsigned p0[3][4], p1[3][4];
            #pragma unroll
            for (int ni = 0; ni < 4; ni++) {
                int off = (wn * 32 + ni * 8 + g) * 20 + ks + tg;
                p0[0][ni] = __float_as_uint(Bs0[off]); p1[0][ni] = __float_as_uint(Bs0[off + 4]);
                p0[1][ni] = __float_as_uint(Bs1[off]); p1[1][ni] = __float_as_uint(Bs1[off + 4]);
                p0[2][ni] = __float_as_uint(Bs2[off]); p1[2][ni] = __float_as_uint(Bs2[off + 4]);
            }
            #pragma unroll
            for (int mi = 0; mi < 2; mi++) {
                int ra = (wm * 32 + mi * 16 + g) * 20 + ks + tg;
                unsigned ae[4] = { __float_as_uint(Ae[ra]), __float_as_uint(Ae[ra + 8 * 20]),
                                   __float_as_uint(Ae[ra + 4]), __float_as_uint(Ae[ra + 8 * 20 + 4]) };
                unsigned ac[4] = { __float_as_uint(Ac[ra]), __float_as_uint(Ac[ra + 8 * 20]),
                                   __float_as_uint(Ac[ra + 4]), __float_as_uint(Ac[ra + 8 * 20 + 4]) };
                unsigned aec[4] = { __float_as_uint(Aec[ra]), __float_as_uint(Aec[ra + 8 * 20]),
                                    __float_as_uint(Aec[ra + 4]), __float_as_uint(Aec[ra + 8 * 20 + 4]) };
                #pragma unroll
                for (int ni = 0; ni < 4; ni++) {
                    mma_tf32(acc[mi][ni], ae, p0[0][ni], p1[0][ni]);
                    mma_tf32(acc[mi][ni], ac, p0[1][ni], p1[1][ni]);
                    mma_tf32(acc[mi][ni], aec, p0[2][ni], p1[2][ni]);
                }
            }
        }
        __syncthreads();
    }

    #pragma unroll
    for (int mi = 0; mi < 2; mi++) {
        int r0 = m0 + wm * 32 + mi * 16 + g;
        int r1 = r0 + 8;
        #pragma unroll
        for (int ni = 0; ni < 4; ni++) {
            int col = n0 + wn * 32 + ni * 8 + 2 * tg;
            if (col < OUT) {
                float* a4 = acc[mi][ni];
                float bi0 = b_red[col], bi1 = b_red[col + 1];
                out[(size_t)r0 * OUT + col] = a4[0] + bi0;
                out[(size_t)r0 * OUT + col + 1] = a4[1] + bi1;
                out[(size_t)r1 * OUT + col] = a4[2] + bi0;
                out[(size_t)r1 * OUT + col + 1] = a4[3] + bi1;
            }
        }
    }
}

// ---------------------------------------------------------------------------
extern "C" void kernel_launch(void* const* d_in, const int* in_sizes, int n_in,
                              void* d_out, int out_size) {
    (void)in_sizes; (void)n_in; (void)out_size;
    const float* emb1  = (const float*)d_in[0];
    const float* emb2  = (const float*)d_in[1];
    const float* w_c   = (const float*)d_in[2];
    const float* b_c   = (const float*)d_in[3];
    const float* w_q   = (const float*)d_in[4];
    const float* b_q   = (const float*)d_in[5];
    const float* w_cq  = (const float*)d_in[6];
    const float* b_cq  = (const float*)d_in[7];
    const float* w_red = (const float*)d_in[8];
    const float* b_red = (const float*)d_in[9];
    float* out = (float*)d_out;

    k_prep1<<<(NA4 + NB4 + 255) / 256, 256>>>(emb1, emb2, w_cq);
    k_prep2<<<dim3(H / 32, QL / 32, B), dim3(32, 8)>>>(emb1);
    k_dots<<<2560, 256>>>(emb1, emb2, w_c, b_c, w_q, b_q);
    k_gemm_s_mma<<<dim3(QL / 128, CL / 128, B), 256>>>(b_cq);
    k_softmax<<<B * CL, 128>>>();
    k_batt<<<B, 256>>>();
    k_q2c_part<<<dim3(H / 128, 8, B), 128>>>(emb2);
    k_q2c_reduce<<<B, 256>>>();
    k_gemm_c2q_mma<<<dim3(H / 128, CL / 128, B), 256>>>();
    k_red_mma<<<dim3((OUT + 63) / 64, (B * CL) / 128), 256>>>(emb2, w_red, b_red, out);
}